// round 7
// baseline (speedup 1.0000x reference)
#include <cuda_runtime.h>
#include <cuda_bf16.h>
#include <math_constants.h>
#include <cstdint>

#define BB 32
#define AA 2048
#define TT 512
#define DD 256
#define TOPK 10

#define MT 64    // articles per block
#define NT 64    // titles per chunk

// Scratch (no cudaMalloc allowed)
__device__ __align__(16) __nv_bfloat16 g_tbf[BB * TT * DD];   // 8.4 MB
__device__ float g_tsq[BB * TT];                              // tsq or +INF if masked
__device__ float g_rowmax[BB * AA];

__device__ __forceinline__ uint32_t smem_u32(const void* p) {
    uint32_t a;
    asm("{ .reg .u64 t; cvta.to.shared.u64 t, %1; cvt.u32.u64 %0, t; }" : "=r"(a) : "l"(p));
    return a;
}

__device__ __forceinline__ void ldsm_x4(uint32_t& r0, uint32_t& r1, uint32_t& r2, uint32_t& r3,
                                        uint32_t addr) {
    asm volatile("ldmatrix.sync.aligned.m8n8.x4.shared.b16 {%0,%1,%2,%3}, [%4];"
                 : "=r"(r0), "=r"(r1), "=r"(r2), "=r"(r3) : "r"(addr));
}

__device__ __forceinline__ void mma_bf16(float* c, uint32_t a0, uint32_t a1, uint32_t a2,
                                         uint32_t a3, uint32_t b0, uint32_t b1) {
    asm volatile("mma.sync.aligned.m16n8k16.row.col.f32.bf16.bf16.f32 "
                 "{%0,%1,%2,%3}, {%4,%5,%6,%7}, {%8,%9}, {%0,%1,%2,%3};"
                 : "+f"(c[0]), "+f"(c[1]), "+f"(c[2]), "+f"(c[3])
                 : "r"(a0), "r"(a1), "r"(a2), "r"(a3), "r"(b0), "r"(b1));
}

// ---------------------------------------------------------------------------
// Title prep: one warp per title row. fp32 -> bf16 (once), sq-norm with
// title mask folded in as +INF sentinel.
// ---------------------------------------------------------------------------
__global__ void title_prep_kernel(const float* __restrict__ title,
                                  const float* __restrict__ tmask) {
    int row = (blockIdx.x * blockDim.x + threadIdx.x) >> 5;
    int lane = threadIdx.x & 31;
    if (row >= BB * TT) return;

    const float4* src = (const float4*)(title + (size_t)row * DD);
    float4 v0 = src[lane * 2 + 0];
    float4 v1 = src[lane * 2 + 1];

    float s = v0.x * v0.x + v0.y * v0.y + v0.z * v0.z + v0.w * v0.w
            + v1.x * v1.x + v1.y * v1.y + v1.z * v1.z + v1.w * v1.w;
#pragma unroll
    for (int o = 16; o; o >>= 1) s += __shfl_xor_sync(0xffffffffu, s, o);
    if (lane == 0)
        g_tsq[row] = (tmask[row] == 0.f) ? CUDART_INF_F : s;

    __nv_bfloat162 h[4];
    h[0] = __float22bfloat162_rn(make_float2(v0.x, v0.y));
    h[1] = __float22bfloat162_rn(make_float2(v0.z, v0.w));
    h[2] = __float22bfloat162_rn(make_float2(v1.x, v1.y));
    h[3] = __float22bfloat162_rn(make_float2(v1.z, v1.w));
    *(int4*)(g_tbf + (size_t)row * DD + lane * 8) = *(int4*)h;
}

// ---------------------------------------------------------------------------
// Fused GEMM: 64-article tile (full K=256 in smem), 8 chunks of 64 titles,
// cp.async double-buffered. 8 warps 4(M) x 2(N), warp tile 16x32 via
// m16n8k16. Swizzle: 512B row, 16B chunk c stored at c ^ (r & 7).
// 2 CTAs/SM (96 KB dynamic smem each) for cross-CTA latency hiding.
// smem: [0,32K) A | [32K,64K) T buf0 | [64K,96K) T buf1
// ---------------------------------------------------------------------------
__global__ void __launch_bounds__(256, 2)
gemm_min_kernel(const float* __restrict__ article,
                const float* __restrict__ amask) {
    extern __shared__ char smem[];
    __shared__ float sAsq[MT];
    __shared__ float sTsq[TT];
    __shared__ float sMin[2][MT];

    const int b   = blockIdx.y;
    const int a0  = blockIdx.x * MT;
    const int tid = threadIdx.x;
    const int lane = tid & 31;
    const int wid  = tid >> 5;
    const int wm   = wid & 3;      // 0..3 : 16-row A group
    const int wn   = wid >> 2;     // 0..1 : 32-col T group

    const uint32_t sA = smem_u32(smem);
    const uint32_t sT0 = sA + MT * 512;            // +32K

    const int r = tid >> 2, q = tid & 3;           // 4 threads per row

    // ---- prefetch T chunk 0 into buf0 (overlaps with A convert below) ----
    {
        const __nv_bfloat16* src = g_tbf + (size_t)(b * TT + r) * DD;
        uint32_t dstbase = sT0 + r * 512;
#pragma unroll
        for (int i = 0; i < 8; i++) {
            int c = q * 8 + i;
            asm volatile("cp.async.cg.shared.global [%0], [%1], 16;"
                         :: "r"(dstbase + ((c ^ (r & 7)) << 4)), "l"(src + c * 8));
        }
        asm volatile("cp.async.commit_group;");
    }

    // ---- all title norms for this batch (512 floats) ----
    sTsq[tid]       = g_tsq[b * TT + tid];
    sTsq[tid + 256] = g_tsq[b * TT + tid + 256];

    // ---- load A tile: fp32 -> bf16 swizzled + sq-norms (4 threads/row) ----
    {
        const float4* src = (const float4*)article + ((size_t)(b * AA + a0 + r) * (DD / 4));
        float ss = 0.f;
#pragma unroll
        for (int i = 0; i < 8; i++) {
            int c = q * 8 + i;                     // 16B chunk index (8 bf16)
            float4 v0 = src[c * 2 + 0];
            float4 v1 = src[c * 2 + 1];
            ss += v0.x * v0.x + v0.y * v0.y + v0.z * v0.z + v0.w * v0.w
                + v1.x * v1.x + v1.y * v1.y + v1.z * v1.z + v1.w * v1.w;
            __nv_bfloat162 hh[4];
            hh[0] = __float22bfloat162_rn(make_float2(v0.x, v0.y));
            hh[1] = __float22bfloat162_rn(make_float2(v0.z, v0.w));
            hh[2] = __float22bfloat162_rn(make_float2(v1.x, v1.y));
            hh[3] = __float22bfloat162_rn(make_float2(v1.z, v1.w));
            *(int4*)(smem + r * 512 + ((c ^ (r & 7)) << 4)) = *(int4*)hh;
        }
        ss += __shfl_xor_sync(0xffffffffu, ss, 1);
        ss += __shfl_xor_sync(0xffffffffu, ss, 2);
        if (q == 0) sAsq[r] = ss;
    }
    __syncthreads();

    // per-thread article rows: wm*16 + (lane>>2) + {0,8}
    float asqv[2], minv[2];
#pragma unroll
    for (int j = 0; j < 2; j++) {
        asqv[j] = sAsq[wm * 16 + (lane >> 2) + 8 * j];
        minv[j] = CUDART_INF_F;
    }

#pragma unroll 1
    for (int tc = 0; tc < TT / NT; tc++) {
        __syncthreads();   // all warps done with the buffer the next prefetch overwrites
        if (tc + 1 < TT / NT) {
            // prefetch chunk tc+1 into alternate buffer
            const __nv_bfloat16* src = g_tbf + (size_t)(b * TT + (tc + 1) * NT + r) * DD;
            uint32_t dstbase = sT0 + ((tc + 1) & 1) * (NT * 512) + r * 512;
#pragma unroll
            for (int i = 0; i < 8; i++) {
                int c = q * 8 + i;
                asm volatile("cp.async.cg.shared.global [%0], [%1], 16;"
                             :: "r"(dstbase + ((c ^ (r & 7)) << 4)), "l"(src + c * 8));
            }
            asm volatile("cp.async.commit_group;");
            asm volatile("cp.async.wait_group 1;");   // chunk tc landed
        } else {
            asm volatile("cp.async.wait_group 0;");   // last chunk landed
        }
        __syncthreads();

        const uint32_t sT = sT0 + (tc & 1) * (NT * 512);

        float acc[4][4];
#pragma unroll
        for (int nt = 0; nt < 4; nt++)
#pragma unroll
            for (int e = 0; e < 4; e++) acc[nt][e] = 0.f;

#pragma unroll
        for (int kk = 0; kk < 16; kk++) {
            const int ch = kk * 2;  // 16B-chunk index of this k16 step
            uint32_t a[4];
            {
                int rr = wm * 16 + (lane & 15);
                int c = ch + (lane >> 4);
                ldsm_x4(a[0], a[1], a[2], a[3],
                        sA + rr * 512 + ((c ^ (rr & 7)) << 4));
            }
            uint32_t bf[4][2];
#pragma unroll
            for (int bt = 0; bt < 2; bt++) {
                int rr = wn * 32 + bt * 16 + ((lane >> 4) << 3) + (lane & 7);
                int c = ch + ((lane >> 3) & 1);
                ldsm_x4(bf[bt * 2][0], bf[bt * 2][1], bf[bt * 2 + 1][0], bf[bt * 2 + 1][1],
                        sT + rr * 512 + ((c ^ (rr & 7)) << 4));
            }
#pragma unroll
            for (int nt = 0; nt < 4; nt++)
                mma_bf16(acc[nt], a[0], a[1], a[2], a[3], bf[nt][0], bf[nt][1]);
        }

        // ---- epilogue: sqdist -> running min (mask already in tsq) ----
        const int tb = tc * NT;
#pragma unroll
        for (int nt = 0; nt < 4; nt++) {
            int cl = tb + wn * 32 + nt * 8 + (lane & 3) * 2;
            float tsq0 = sTsq[cl];
            float tsq1 = sTsq[cl + 1];
#pragma unroll
            for (int j = 0; j < 2; j++) {          // j=0 -> row g, j=1 -> g+8
                float sq0 = asqv[j] + tsq0 - 2.f * acc[nt][j * 2 + 0];
                float sq1 = asqv[j] + tsq1 - 2.f * acc[nt][j * 2 + 1];
                minv[j] = fminf(minv[j], fminf(sq0, sq1));
            }
        }
    }

    // reduce min across the 4 lanes sharing rows (different col groups)
#pragma unroll
    for (int j = 0; j < 2; j++) {
        minv[j] = fminf(minv[j], __shfl_xor_sync(0xffffffffu, minv[j], 1));
        minv[j] = fminf(minv[j], __shfl_xor_sync(0xffffffffu, minv[j], 2));
    }
    if ((lane & 3) == 0) {
#pragma unroll
        for (int j = 0; j < 2; j++)
            sMin[wn][wm * 16 + (lane >> 2) + 8 * j] = minv[j];
    }
    __syncthreads();
    if (tid < MT) {
        float m = fminf(sMin[0][tid], sMin[1][tid]);
        int a = a0 + tid;
        g_rowmax[b * AA + a] = amask[b * AA + a] * expf(-m);
    }
}

// ---------------------------------------------------------------------------
// Per-batch top-10 (iterative selection, descending) + tiny MLP
// ---------------------------------------------------------------------------
__global__ void topk_mlp_kernel(const float* __restrict__ W1,
                                const float* __restrict__ b1,
                                const float* __restrict__ W2,
                                const float* __restrict__ b2,
                                float* __restrict__ out) {
    __shared__ float vals[AA];
    __shared__ float rmax[256];
    __shared__ int   ridx[256];
    __shared__ float top[TOPK];

    const int b = blockIdx.x;
    const int tid = threadIdx.x;

    for (int i = tid; i < AA; i += 256) vals[i] = g_rowmax[b * AA + i];
    __syncthreads();

    for (int k = 0; k < TOPK; k++) {
        float mv = -1.f; int mi = 0;
        for (int i = tid; i < AA; i += 256) {
            float v = vals[i];
            if (v > mv) { mv = v; mi = i; }
        }
        rmax[tid] = mv; ridx[tid] = mi;
        __syncthreads();
        for (int s = 128; s; s >>= 1) {
            if (tid < s && rmax[tid + s] > rmax[tid]) {
                rmax[tid] = rmax[tid + s]; ridx[tid] = ridx[tid + s];
            }
            __syncthreads();
        }
        if (tid == 0) { top[k] = rmax[0]; vals[ridx[0]] = -2.f; }
        __syncthreads();
    }

    if (tid == 0) {
        float o = b2[0];
#pragma unroll
        for (int i = 0; i < TOPK; i++) {
            float h = b1[i];
#pragma unroll
            for (int j = 0; j < TOPK; j++) h += W1[i * TOPK + j] * top[j];
            o += W2[i] * fmaxf(h, 0.f);
        }
        out[b] = o;
    }
}

// ---------------------------------------------------------------------------
extern "C" void kernel_launch(void* const* d_in, const int* in_sizes, int n_in,
                              void* d_out, int out_size) {
    const float* article = (const float*)d_in[0];
    const float* title   = (const float*)d_in[1];
    const float* amask   = (const float*)d_in[2];
    const float* tmask   = (const float*)d_in[3];
    const float* W1      = (const float*)d_in[4];
    const float* b1      = (const float*)d_in[5];
    const float* W2      = (const float*)d_in[6];
    const float* b2      = (const float*)d_in[7];
    float* out = (float*)d_out;

    // 1) title prep: bf16 + (masked) sq-norms, once
    title_prep_kernel<<<(BB * TT * 32 + 255) / 256, 256>>>(title, tmask);

    // 2) fused article-convert + HMMA GEMM (cp.async double-buffered T) + min + exp
    const int smem = 3 * MT * 512;   // 96 KB dynamic: A + 2x T
    cudaFuncSetAttribute(gemm_min_kernel, cudaFuncAttributeMaxDynamicSharedMemorySize, smem);
    gemm_min_kernel<<<dim3(AA / MT, BB), 256, smem>>>(article, amask);

    // 3) top-k + MLP
    topk_mlp_kernel<<<BB, 256>>>(W1, b1, W2, b2, out);
}

// round 10
// speedup vs baseline: 1.5173x; 1.5173x over previous
#include <cuda_runtime.h>
#include <cuda_bf16.h>
#include <math_constants.h>
#include <cstdint>

#define BB 32
#define AA 2048
#define TT 512
#define DD 256
#define TOPK 10

#define MT 64    // articles per block
#define NT 64    // titles per chunk (8 chunks)

// Scratch (no cudaMalloc allowed)
__device__ __align__(16) uint8_t g_tf8[BB * TT * DD];   // 4.2 MB, e4m3 titles
__device__ float g_tsq[BB * TT];                        // tsq or +INF if masked
__device__ float g_rowmax[BB * AA];

__device__ __forceinline__ uint32_t smem_u32(const void* p) {
    uint32_t a;
    asm("{ .reg .u64 t; cvta.to.shared.u64 t, %1; cvt.u32.u64 %0, t; }" : "=r"(a) : "l"(p));
    return a;
}

__device__ __forceinline__ void ldsm_x4(uint32_t& r0, uint32_t& r1, uint32_t& r2, uint32_t& r3,
                                        uint32_t addr) {
    asm volatile("ldmatrix.sync.aligned.m8n8.x4.shared.b16 {%0,%1,%2,%3}, [%4];"
                 : "=r"(r0), "=r"(r1), "=r"(r2), "=r"(r3) : "r"(addr));
}

// fp8 e4m3 MMA, m16n8k32, f32 accumulate
__device__ __forceinline__ void mma_fp8(float* c, uint32_t a0, uint32_t a1, uint32_t a2,
                                        uint32_t a3, uint32_t b0, uint32_t b1) {
    asm volatile("mma.sync.aligned.m16n8k32.row.col.f32.e4m3.e4m3.f32 "
                 "{%0,%1,%2,%3}, {%4,%5,%6,%7}, {%8,%9}, {%0,%1,%2,%3};"
                 : "+f"(c[0]), "+f"(c[1]), "+f"(c[2]), "+f"(c[3])
                 : "r"(a0), "r"(a1), "r"(a2), "r"(a3), "r"(b0), "r"(b1));
}

// pack 4 consecutive floats -> 4 e4m3 bytes (memory order preserved)
__device__ __forceinline__ uint32_t cvt4_e4m3(float f0, float f1, float f2, float f3) {
    uint16_t lo, hi;
    asm("cvt.rn.satfinite.e4m3x2.f32 %0, %1, %2;" : "=h"(lo) : "f"(f1), "f"(f0));
    asm("cvt.rn.satfinite.e4m3x2.f32 %0, %1, %2;" : "=h"(hi) : "f"(f3), "f"(f2));
    return (uint32_t)lo | ((uint32_t)hi << 16);
}

// ---------------------------------------------------------------------------
// Title prep: one warp per title row. fp32 -> e4m3 (once), sq-norm with
// title mask folded in as +INF sentinel.
// ---------------------------------------------------------------------------
__global__ void title_prep_kernel(const float* __restrict__ title,
                                  const float* __restrict__ tmask) {
    int row = (blockIdx.x * blockDim.x + threadIdx.x) >> 5;
    int lane = threadIdx.x & 31;
    if (row >= BB * TT) return;

    const float4* src = (const float4*)(title + (size_t)row * DD);
    float4 v0 = src[lane * 2 + 0];
    float4 v1 = src[lane * 2 + 1];

    float s = v0.x * v0.x + v0.y * v0.y + v0.z * v0.z + v0.w * v0.w
            + v1.x * v1.x + v1.y * v1.y + v1.z * v1.z + v1.w * v1.w;
#pragma unroll
    for (int o = 16; o; o >>= 1) s += __shfl_xor_sync(0xffffffffu, s, o);
    if (lane == 0)
        g_tsq[row] = (tmask[row] == 0.f) ? CUDART_INF_F : s;

    uint2 p;
    p.x = cvt4_e4m3(v0.x, v0.y, v0.z, v0.w);
    p.y = cvt4_e4m3(v1.x, v1.y, v1.z, v1.w);
    *(uint2*)(g_tf8 + (size_t)row * DD + lane * 8) = p;
}

// ---------------------------------------------------------------------------
// FP8 MMA GEMM: 64-article tile (full K=256 e4m3 = 256B/row in smem),
// 8 chunks of 64 titles, cp.async double-buffered. 8 warps 4(M) x 2(N),
// warp tile 16x32 via m16n8k32.e4m3 (8 k-steps). Swizzle: 256B row, 16B
// chunk c stored at c ^ (r & 7). 4 CTAs/SM (48 KB each).
// smem: [0,16K) A | [16K,32K) T buf0 | [32K,48K) T buf1
// ---------------------------------------------------------------------------
__global__ void __launch_bounds__(256, 4)
gemm_min_kernel(const float* __restrict__ article,
                const float* __restrict__ amask) {
    extern __shared__ char smem[];
    __shared__ float sAsq[MT];
    __shared__ float sTsq[TT];
    __shared__ float sMin[2][MT];

    const int b   = blockIdx.y;
    const int a0  = blockIdx.x * MT;
    const int tid = threadIdx.x;
    const int lane = tid & 31;
    const int wid  = tid >> 5;
    const int wm   = wid & 3;      // 0..3 : 16-row A group
    const int wn   = wid >> 2;     // 0..1 : 32-col T group

    const uint32_t sA = smem_u32(smem);
    const uint32_t sT0 = sA + MT * 256;            // +16K

    const int r = tid >> 2, q = tid & 3;           // 4 threads per row, 4 chunks each

    // ---- prefetch T chunk 0 into buf0 (overlaps with A convert below) ----
    {
        const uint8_t* src = g_tf8 + (size_t)(b * TT + r) * DD;
        uint32_t dstbase = sT0 + r * 256;
#pragma unroll
        for (int i = 0; i < 4; i++) {
            int c = q * 4 + i;
            asm volatile("cp.async.cg.shared.global [%0], [%1], 16;"
                         :: "r"(dstbase + ((c ^ (r & 7)) << 4)), "l"(src + c * 16));
        }
        asm volatile("cp.async.commit_group;");
    }

    // ---- all title norms for this batch (512 floats) ----
    sTsq[tid]       = g_tsq[b * TT + tid];
    sTsq[tid + 256] = g_tsq[b * TT + tid + 256];

    // ---- load A tile: fp32 -> e4m3 swizzled + sq-norms (4 threads/row) ----
    {
        const float4* src = (const float4*)article + ((size_t)(b * AA + a0 + r) * (DD / 4));
        float ss = 0.f;
#pragma unroll
        for (int i = 0; i < 4; i++) {
            int c = q * 4 + i;                     // 16B chunk = 16 e4m3 = 16 floats
            float4 v0 = src[c * 4 + 0];
            float4 v1 = src[c * 4 + 1];
            float4 v2 = src[c * 4 + 2];
            float4 v3 = src[c * 4 + 3];
            ss += v0.x * v0.x + v0.y * v0.y + v0.z * v0.z + v0.w * v0.w
                + v1.x * v1.x + v1.y * v1.y + v1.z * v1.z + v1.w * v1.w
                + v2.x * v2.x + v2.y * v2.y + v2.z * v2.z + v2.w * v2.w
                + v3.x * v3.x + v3.y * v3.y + v3.z * v3.z + v3.w * v3.w;
            uint4 pk;
            pk.x = cvt4_e4m3(v0.x, v0.y, v0.z, v0.w);
            pk.y = cvt4_e4m3(v1.x, v1.y, v1.z, v1.w);
            pk.z = cvt4_e4m3(v2.x, v2.y, v2.z, v2.w);
            pk.w = cvt4_e4m3(v3.x, v3.y, v3.z, v3.w);
            *(uint4*)(smem + r * 256 + ((c ^ (r & 7)) << 4)) = pk;
        }
        ss += __shfl_xor_sync(0xffffffffu, ss, 1);
        ss += __shfl_xor_sync(0xffffffffu, ss, 2);
        if (q == 0) sAsq[r] = ss;
    }
    __syncthreads();

    // per-thread article rows: wm*16 + (lane>>2) + {0,8}
    float asqv[2], minv[2];
#pragma unroll
    for (int j = 0; j < 2; j++) {
        asqv[j] = sAsq[wm * 16 + (lane >> 2) + 8 * j];
        minv[j] = CUDART_INF_F;
    }

#pragma unroll 1
    for (int tc = 0; tc < TT / NT; tc++) {
        __syncthreads();   // all warps done with the buffer the next prefetch overwrites
        if (tc + 1 < TT / NT) {
            // prefetch chunk tc+1 into alternate buffer
            const uint8_t* src = g_tf8 + (size_t)(b * TT + (tc + 1) * NT + r) * DD;
            uint32_t dstbase = sT0 + ((tc + 1) & 1) * (NT * 256) + r * 256;
#pragma unroll
            for (int i = 0; i < 4; i++) {
                int c = q * 4 + i;
                asm volatile("cp.async.cg.shared.global [%0], [%1], 16;"
                             :: "r"(dstbase + ((c ^ (r & 7)) << 4)), "l"(src + c * 16));
            }
            asm volatile("cp.async.commit_group;");
            asm volatile("cp.async.wait_group 1;");   // chunk tc landed
        } else {
            asm volatile("cp.async.wait_group 0;");   // last chunk landed
        }
        __syncthreads();

        const uint32_t sT = sT0 + (tc & 1) * (NT * 256);

        float acc[4][4];
#pragma unroll
        for (int nt = 0; nt < 4; nt++)
#pragma unroll
            for (int e = 0; e < 4; e++) acc[nt][e] = 0.f;

#pragma unroll
        for (int kk = 0; kk < 8; kk++) {           // k32 per step: chunks (2kk, 2kk+1)
            const int ch = kk * 2;
            uint32_t a[4];
            {
                int rr = wm * 16 + (lane & 15);
                int c = ch + (lane >> 4);
                ldsm_x4(a[0], a[1], a[2], a[3],
                        sA + rr * 256 + ((c ^ (rr & 7)) << 4));
            }
            uint32_t bf[4][2];
#pragma unroll
            for (int bt = 0; bt < 2; bt++) {
                int rr = wn * 32 + bt * 16 + ((lane >> 4) << 3) + (lane & 7);
                int c = ch + ((lane >> 3) & 1);
                ldsm_x4(bf[bt * 2][0], bf[bt * 2][1], bf[bt * 2 + 1][0], bf[bt * 2 + 1][1],
                        sT + rr * 256 + ((c ^ (rr & 7)) << 4));
            }
#pragma unroll
            for (int nt = 0; nt < 4; nt++)
                mma_fp8(acc[nt], a[0], a[1], a[2], a[3], bf[nt][0], bf[nt][1]);
        }

        // ---- epilogue: sqdist -> running min (mask already in tsq) ----
        const int tb = tc * NT;
#pragma unroll
        for (int nt = 0; nt < 4; nt++) {
            int cl = tb + wn * 32 + nt * 8 + (lane & 3) * 2;
            float tsq0 = sTsq[cl];
            float tsq1 = sTsq[cl + 1];
#pragma unroll
            for (int j = 0; j < 2; j++) {          // j=0 -> row g, j=1 -> g+8
                float sq0 = asqv[j] + tsq0 - 2.f * acc[nt][j * 2 + 0];
                float sq1 = asqv[j] + tsq1 - 2.f * acc[nt][j * 2 + 1];
                minv[j] = fminf(minv[j], fminf(sq0, sq1));
            }
        }
    }

    // reduce min across the 4 lanes sharing rows (different col groups)
#pragma unroll
    for (int j = 0; j < 2; j++) {
        minv[j] = fminf(minv[j], __shfl_xor_sync(0xffffffffu, minv[j], 1));
        minv[j] = fminf(minv[j], __shfl_xor_sync(0xffffffffu, minv[j], 2));
    }
    if ((lane & 3) == 0) {
#pragma unroll
        for (int j = 0; j < 2; j++)
            sMin[wn][wm * 16 + (lane >> 2) + 8 * j] = minv[j];
    }
    __syncthreads();
    if (tid < MT) {
        float m = fminf(sMin[0][tid], sMin[1][tid]);
        int a = a0 + tid;
        g_rowmax[b * AA + a] = amask[b * AA + a] * expf(-m);
    }
}

// ---------------------------------------------------------------------------
// Per-batch top-10 (iterative selection, descending) + tiny MLP
// ---------------------------------------------------------------------------
__global__ void topk_mlp_kernel(const float* __restrict__ W1,
                                const float* __restrict__ b1,
                                const float* __restrict__ W2,
                                const float* __restrict__ b2,
                                float* __restrict__ out) {
    __shared__ float vals[AA];
    __shared__ float rmax[256];
    __shared__ int   ridx[256];
    __shared__ float top[TOPK];

    const int b = blockIdx.x;
    const int tid = threadIdx.x;

    for (int i = tid; i < AA; i += 256) vals[i] = g_rowmax[b * AA + i];
    __syncthreads();

    for (int k = 0; k < TOPK; k++) {
        float mv = -1.f; int mi = 0;
        for (int i = tid; i < AA; i += 256) {
            float v = vals[i];
            if (v > mv) { mv = v; mi = i; }
        }
        rmax[tid] = mv; ridx[tid] = mi;
        __syncthreads();
        for (int s = 128; s; s >>= 1) {
            if (tid < s && rmax[tid + s] > rmax[tid]) {
                rmax[tid] = rmax[tid + s]; ridx[tid] = ridx[tid + s];
            }
            __syncthreads();
        }
        if (tid == 0) { top[k] = rmax[0]; vals[ridx[0]] = -2.f; }
        __syncthreads();
    }

    if (tid == 0) {
        float o = b2[0];
#pragma unroll
        for (int i = 0; i < TOPK; i++) {
            float h = b1[i];
#pragma unroll
            for (int j = 0; j < TOPK; j++) h += W1[i * TOPK + j] * top[j];
            o += W2[i] * fmaxf(h, 0.f);
        }
        out[b] = o;
    }
}

// ---------------------------------------------------------------------------
extern "C" void kernel_launch(void* const* d_in, const int* in_sizes, int n_in,
                              void* d_out, int out_size) {
    const float* article = (const float*)d_in[0];
    const float* title   = (const float*)d_in[1];
    const float* amask   = (const float*)d_in[2];
    const float* tmask   = (const float*)d_in[3];
    const float* W1      = (const float*)d_in[4];
    const float* b1      = (const float*)d_in[5];
    const float* W2      = (const float*)d_in[6];
    const float* b2      = (const float*)d_in[7];
    float* out = (float*)d_out;

    // 1) title prep: e4m3 + (masked) sq-norms, once
    title_prep_kernel<<<(BB * TT * 32 + 255) / 256, 256>>>(title, tmask);

    // 2) fused article-convert + FP8 MMA GEMM (cp.async double-buffered T) + min + exp
    const int smem = 3 * MT * 256;   // 48 KB dynamic: A + 2x T
    cudaFuncSetAttribute(gemm_min_kernel, cudaFuncAttributeMaxDynamicSharedMemorySize, smem);
    gemm_min_kernel<<<dim3(AA / MT, BB), 256, smem>>>(article, amask);

    // 3) top-k + MLP
    topk_mlp_kernel<<<BB, 256>>>(W1, b1, W2, b2, out);
}

// round 12
// speedup vs baseline: 1.6126x; 1.0629x over previous
#include <cuda_runtime.h>
#include <cuda_bf16.h>
#include <cuda_fp16.h>
#include <math_constants.h>
#include <cstdint>

#define BB 32
#define AA 2048
#define TT 512
#define DD 256
#define TOPK 10

#define MT 64    // articles per block
#define NT 64    // titles per chunk (8 chunks)

// Scratch (no cudaMalloc allowed)
__device__ __align__(16) uint8_t g_tf8[BB * TT * DD];   // 4.2 MB, e4m3 titles
__device__ float g_tsq[BB * TT];                        // tsq or +INF if masked
__device__ float g_rowmax[BB * AA];

__device__ __forceinline__ uint32_t smem_u32(const void* p) {
    uint32_t a;
    asm("{ .reg .u64 t; cvta.to.shared.u64 t, %1; cvt.u32.u64 %0, t; }" : "=r"(a) : "l"(p));
    return a;
}

__device__ __forceinline__ void ldsm_x4(uint32_t& r0, uint32_t& r1, uint32_t& r2, uint32_t& r3,
                                        uint32_t addr) {
    asm volatile("ldmatrix.sync.aligned.m8n8.x4.shared.b16 {%0,%1,%2,%3}, [%4];"
                 : "=r"(r0), "=r"(r1), "=r"(r2), "=r"(r3) : "r"(addr));
}

// fp8 e4m3 MMA, m16n8k32, f16 accumulate (2x rate vs f32 accum).
// c[0] = half2 (row g,  col 2t | col 2t+1), c[1] = half2 (row g+8, ...)
__device__ __forceinline__ void mma_fp8_f16(uint32_t* c, uint32_t a0, uint32_t a1, uint32_t a2,
                                            uint32_t a3, uint32_t b0, uint32_t b1) {
    asm volatile("mma.sync.aligned.m16n8k32.row.col.f16.e4m3.e4m3.f16 "
                 "{%0,%1}, {%2,%3,%4,%5}, {%6,%7}, {%0,%1};"
                 : "+r"(c[0]), "+r"(c[1])
                 : "r"(a0), "r"(a1), "r"(a2), "r"(a3), "r"(b0), "r"(b1));
}

// pack 4 consecutive floats -> 4 e4m3 bytes (memory order preserved)
__device__ __forceinline__ uint32_t cvt4_e4m3(float f0, float f1, float f2, float f3) {
    uint16_t lo, hi;
    asm("cvt.rn.satfinite.e4m3x2.f32 %0, %1, %2;" : "=h"(lo) : "f"(f1), "f"(f0));
    asm("cvt.rn.satfinite.e4m3x2.f32 %0, %1, %2;" : "=h"(hi) : "f"(f3), "f"(f2));
    return (uint32_t)lo | ((uint32_t)hi << 16);
}

// ---------------------------------------------------------------------------
// Title prep: one warp per title row. fp32 -> e4m3 (once), sq-norm with
// title mask folded in as +INF sentinel.
// ---------------------------------------------------------------------------
__global__ void title_prep_kernel(const float* __restrict__ title,
                                  const float* __restrict__ tmask) {
    int row = (blockIdx.x * blockDim.x + threadIdx.x) >> 5;
    int lane = threadIdx.x & 31;
    if (row >= BB * TT) return;

    const float4* src = (const float4*)(title + (size_t)row * DD);
    float4 v0 = src[lane * 2 + 0];
    float4 v1 = src[lane * 2 + 1];

    float s = v0.x * v0.x + v0.y * v0.y + v0.z * v0.z + v0.w * v0.w
            + v1.x * v1.x + v1.y * v1.y + v1.z * v1.z + v1.w * v1.w;
#pragma unroll
    for (int o = 16; o; o >>= 1) s += __shfl_xor_sync(0xffffffffu, s, o);
    if (lane == 0)
        g_tsq[row] = (tmask[row] == 0.f) ? CUDART_INF_F : s;

    uint2 p;
    p.x = cvt4_e4m3(v0.x, v0.y, v0.z, v0.w);
    p.y = cvt4_e4m3(v1.x, v1.y, v1.z, v1.w);
    *(uint2*)(g_tf8 + (size_t)row * DD + lane * 8) = p;
}

// ---------------------------------------------------------------------------
// FP8 MMA GEMM (f16 accum): 64-article tile (full K=256 e4m3 = 256B/row in
// smem), 8 chunks of 64 titles, cp.async double-buffered. 8 warps 4(M) x
// 2(N), warp tile 16x32 via m16n8k32.e4m3 (8 k-steps). Swizzle: 256B row,
// 16B chunk c stored at c ^ (r & 7). 4 CTAs/SM (48 KB each).
// smem: [0,16K) A | [16K,32K) T buf0 | [32K,48K) T buf1
// ---------------------------------------------------------------------------
__global__ void __launch_bounds__(256, 4)
gemm_min_kernel(const float* __restrict__ article,
                const float* __restrict__ amask) {
    extern __shared__ char smem[];
    __shared__ float sAsq[MT];
    __shared__ float sTsq[TT];
    __shared__ float sMin[2][MT];

    const int b   = blockIdx.y;
    const int a0  = blockIdx.x * MT;
    const int tid = threadIdx.x;
    const int lane = tid & 31;
    const int wid  = tid >> 5;
    const int wm   = wid & 3;      // 0..3 : 16-row A group
    const int wn   = wid >> 2;     // 0..1 : 32-col T group

    const uint32_t sA = smem_u32(smem);
    const uint32_t sT0 = sA + MT * 256;            // +16K

    const int r = tid >> 2, q = tid & 3;           // 4 threads per row, 4 chunks each

    // ---- prefetch T chunk 0 into buf0 (overlaps with A convert below) ----
    {
        const uint8_t* src = g_tf8 + (size_t)(b * TT + r) * DD;
        uint32_t dstbase = sT0 + r * 256;
#pragma unroll
        for (int i = 0; i < 4; i++) {
            int c = q * 4 + i;
            asm volatile("cp.async.cg.shared.global [%0], [%1], 16;"
                         :: "r"(dstbase + ((c ^ (r & 7)) << 4)), "l"(src + c * 16));
        }
        asm volatile("cp.async.commit_group;");
    }

    // ---- all title norms for this batch (512 floats) ----
    sTsq[tid]       = g_tsq[b * TT + tid];
    sTsq[tid + 256] = g_tsq[b * TT + tid + 256];

    // ---- load A tile: fp32 -> e4m3 swizzled + sq-norms (4 threads/row) ----
    {
        const float4* src = (const float4*)article + ((size_t)(b * AA + a0 + r) * (DD / 4));
        float ss = 0.f;
#pragma unroll
        for (int i = 0; i < 4; i++) {
            int c = q * 4 + i;                     // 16B chunk = 16 e4m3 = 16 floats
            float4 v0 = src[c * 4 + 0];
            float4 v1 = src[c * 4 + 1];
            float4 v2 = src[c * 4 + 2];
            float4 v3 = src[c * 4 + 3];
            ss += v0.x * v0.x + v0.y * v0.y + v0.z * v0.z + v0.w * v0.w
                + v1.x * v1.x + v1.y * v1.y + v1.z * v1.z + v1.w * v1.w
                + v2.x * v2.x + v2.y * v2.y + v2.z * v2.z + v2.w * v2.w
                + v3.x * v3.x + v3.y * v3.y + v3.z * v3.z + v3.w * v3.w;
            uint4 pk;
            pk.x = cvt4_e4m3(v0.x, v0.y, v0.z, v0.w);
            pk.y = cvt4_e4m3(v1.x, v1.y, v1.z, v1.w);
            pk.z = cvt4_e4m3(v2.x, v2.y, v2.z, v2.w);
            pk.w = cvt4_e4m3(v3.x, v3.y, v3.z, v3.w);
            *(uint4*)(smem + r * 256 + ((c ^ (r & 7)) << 4)) = pk;
        }
        ss += __shfl_xor_sync(0xffffffffu, ss, 1);
        ss += __shfl_xor_sync(0xffffffffu, ss, 2);
        if (q == 0) sAsq[r] = ss;
    }
    __syncthreads();

    // per-thread article rows: wm*16 + (lane>>2) + {0,8}
    float asqv[2], minv[2];
#pragma unroll
    for (int j = 0; j < 2; j++) {
        asqv[j] = sAsq[wm * 16 + (lane >> 2) + 8 * j];
        minv[j] = CUDART_INF_F;
    }

#pragma unroll 1
    for (int tc = 0; tc < TT / NT; tc++) {
        __syncthreads();   // all warps done with the buffer the next prefetch overwrites
        if (tc + 1 < TT / NT) {
            // prefetch chunk tc+1 into alternate buffer
            const uint8_t* src = g_tf8 + (size_t)(b * TT + (tc + 1) * NT + r) * DD;
            uint32_t dstbase = sT0 + ((tc + 1) & 1) * (NT * 256) + r * 256;
#pragma unroll
            for (int i = 0; i < 4; i++) {
                int c = q * 4 + i;
                asm volatile("cp.async.cg.shared.global [%0], [%1], 16;"
                             :: "r"(dstbase + ((c ^ (r & 7)) << 4)), "l"(src + c * 16));
            }
            asm volatile("cp.async.commit_group;");
            asm volatile("cp.async.wait_group 1;");   // chunk tc landed
        } else {
            asm volatile("cp.async.wait_group 0;");   // last chunk landed
        }
        __syncthreads();

        const uint32_t sT = sT0 + (tc & 1) * (NT * 256);

        uint32_t acc[4][2];   // f16x2 accumulators
#pragma unroll
        for (int nt = 0; nt < 4; nt++) { acc[nt][0] = 0u; acc[nt][1] = 0u; }

#pragma unroll
        for (int kk = 0; kk < 8; kk++) {           // k32 per step: chunks (2kk, 2kk+1)
            const int ch = kk * 2;
            uint32_t a[4];
            {
                int rr = wm * 16 + (lane & 15);
                int c = ch + (lane >> 4);
                ldsm_x4(a[0], a[1], a[2], a[3],
                        sA + rr * 256 + ((c ^ (rr & 7)) << 4));
            }
            uint32_t bf[4][2];
#pragma unroll
            for (int bt = 0; bt < 2; bt++) {
                int rr = wn * 32 + bt * 16 + ((lane >> 4) << 3) + (lane & 7);
                int c = ch + ((lane >> 3) & 1);
                ldsm_x4(bf[bt * 2][0], bf[bt * 2][1], bf[bt * 2 + 1][0], bf[bt * 2 + 1][1],
                        sT + rr * 256 + ((c ^ (rr & 7)) << 4));
            }
#pragma unroll
            for (int nt = 0; nt < 4; nt++)
                mma_fp8_f16(acc[nt], a[0], a[1], a[2], a[3], bf[nt][0], bf[nt][1]);
        }

        // ---- epilogue: sqdist -> running min (mask already in tsq) ----
        const int tb = tc * NT;
#pragma unroll
        for (int nt = 0; nt < 4; nt++) {
            int cl = tb + wn * 32 + nt * 8 + (lane & 3) * 2;
            float tsq0 = sTsq[cl];
            float tsq1 = sTsq[cl + 1];
#pragma unroll
            for (int j = 0; j < 2; j++) {          // j=0 -> row g, j=1 -> g+8
                float2 cv = __half22float2(*(const __half2*)&acc[nt][j]);
                float sq0 = asqv[j] + tsq0 - 2.f * cv.x;
                float sq1 = asqv[j] + tsq1 - 2.f * cv.y;
                minv[j] = fminf(minv[j], fminf(sq0, sq1));
            }
        }
    }

    // reduce min across the 4 lanes sharing rows (different col groups)
#pragma unroll
    for (int j = 0; j < 2; j++) {
        minv[j] = fminf(minv[j], __shfl_xor_sync(0xffffffffu, minv[j], 1));
        minv[j] = fminf(minv[j], __shfl_xor_sync(0xffffffffu, minv[j], 2));
    }
    if ((lane & 3) == 0) {
#pragma unroll
        for (int j = 0; j < 2; j++)
            sMin[wn][wm * 16 + (lane >> 2) + 8 * j] = minv[j];
    }
    __syncthreads();
    if (tid < MT) {
        float m = fminf(sMin[0][tid], sMin[1][tid]);
        int a = a0 + tid;
        g_rowmax[b * AA + a] = amask[b * AA + a] * expf(-m);
    }
}

// ---------------------------------------------------------------------------
// Per-batch top-10 (iterative selection, descending) + tiny MLP
// ---------------------------------------------------------------------------
__global__ void topk_mlp_kernel(const float* __restrict__ W1,
                                const float* __restrict__ b1,
                                const float* __restrict__ W2,
                                const float* __restrict__ b2,
                                float* __restrict__ out) {
    __shared__ float vals[AA];
    __shared__ float rmax[256];
    __shared__ int   ridx[256];
    __shared__ float top[TOPK];

    const int b = blockIdx.x;
    const int tid = threadIdx.x;

    for (int i = tid; i < AA; i += 256) vals[i] = g_rowmax[b * AA + i];
    __syncthreads();

    for (int k = 0; k < TOPK; k++) {
        float mv = -1.f; int mi = 0;
        for (int i = tid; i < AA; i += 256) {
            float v = vals[i];
            if (v > mv) { mv = v; mi = i; }
        }
        rmax[tid] = mv; ridx[tid] = mi;
        __syncthreads();
        for (int s = 128; s; s >>= 1) {
            if (tid < s && rmax[tid + s] > rmax[tid]) {
                rmax[tid] = rmax[tid + s]; ridx[tid] = ridx[tid + s];
            }
            __syncthreads();
        }
        if (tid == 0) { top[k] = rmax[0]; vals[ridx[0]] = -2.f; }
        __syncthreads();
    }

    if (tid == 0) {
        float o = b2[0];
#pragma unroll
        for (int i = 0; i < TOPK; i++) {
            float h = b1[i];
#pragma unroll
            for (int j = 0; j < TOPK; j++) h += W1[i * TOPK + j] * top[j];
            o += W2[i] * fmaxf(h, 0.f);
        }
        out[b] = o;
    }
}

// ---------------------------------------------------------------------------
extern "C" void kernel_launch(void* const* d_in, const int* in_sizes, int n_in,
                              void* d_out, int out_size) {
    const float* article = (const float*)d_in[0];
    const float* title   = (const float*)d_in[1];
    const float* amask   = (const float*)d_in[2];
    const float* tmask   = (const float*)d_in[3];
    const float* W1      = (const float*)d_in[4];
    const float* b1      = (const float*)d_in[5];
    const float* W2      = (const float*)d_in[6];
    const float* b2      = (const float*)d_in[7];
    float* out = (float*)d_out;

    // 1) title prep: e4m3 + (masked) sq-norms, once
    title_prep_kernel<<<(BB * TT * 32 + 255) / 256, 256>>>(title, tmask);

    // 2) fused article-convert + FP8 MMA GEMM (f16 accum, cp.async double-buffered)
    const int smem = 3 * MT * 256;   // 48 KB dynamic: A + 2x T
    cudaFuncSetAttribute(gemm_min_kernel, cudaFuncAttributeMaxDynamicSharedMemorySize, smem);
    gemm_min_kernel<<<dim3(AA / MT, BB), 256, smem>>>(article, amask);

    // 3) top-k + MLP
    topk_mlp_kernel<<<BB, 256>>>(W1, b1, W2, b2, out);
}